// round 13
// baseline (speedup 1.0000x reference)
#include <cuda_runtime.h>
#include <math.h>
#include <stdint.h>

#define NG 10000      // genes
#define NC 8192       // cells
#define ZD 100        // z dim
#define KD 32         // key dim
#define HD 256        // hidden dim (key MLP)
#define GT 128        // genes per CTA (= M)
#define CT 64         // cells per chunk
#define NSPLIT 16     // cell splits
#define CPC (NC / NSPLIT)        // 512 cells per CTA
#define NCHUNK (CPC / CT)        // 8 chunks
#define THREADS 256

#define KSTR 36       // Ks row stride (floats)
#define VSTR 68       // Vs row stride (z-major: [z][cell])
#define GSTR 68       // Gs row stride
#define PSTR 68       // Ps row stride

// log2(e), log2(e)/sqrt(32)
#define L2E 1.4426950408889634f
#define SCALE_S 0.25503482f

typedef unsigned long long u64;

__device__ __forceinline__ uint32_t smem_u32(const void* p) {
    uint32_t a;
    asm("{ .reg .u64 t; cvta.to.shared.u64 t, %1; cvt.u32.u64 %0, t; }" : "=r"(a) : "l"(p));
    return a;
}

__device__ __forceinline__ float to_tf32(float x) {
    uint32_t r;
    asm("cvt.rna.tf32.f32 %0, %1;" : "=r"(r) : "f"(x));
    return __uint_as_float(r);
}

__device__ __forceinline__ void cpa16(uint32_t dst, const void* src) {
    asm volatile("cp.async.cg.shared.global [%0], [%1], 16;" :: "r"(dst), "l"(src));
}
#define CPA_COMMIT() asm volatile("cp.async.commit_group;" ::: "memory")
#define CPA_WAIT0()  asm volatile("cp.async.wait_group 0;" ::: "memory")
#define CPA_WAIT1()  asm volatile("cp.async.wait_group 1;" ::: "memory")

__device__ __forceinline__ void ldmx4(uint32_t* r, uint32_t addr) {
    asm volatile("ldmatrix.sync.aligned.m8n8.x4.shared.b16 {%0,%1,%2,%3}, [%4];"
        : "=r"(r[0]), "=r"(r[1]), "=r"(r[2]), "=r"(r[3]) : "r"(addr));
}
__device__ __forceinline__ void ldmx2(uint32_t* r, uint32_t addr) {
    asm volatile("ldmatrix.sync.aligned.m8n8.x2.shared.b16 {%0,%1}, [%2];"
        : "=r"(r[0]), "=r"(r[1]) : "r"(addr));
}

// m16n8k8 tf32 mma, C=D accum
__device__ __forceinline__ void mma_tf32(float* c,
                                         uint32_t a0, uint32_t a1, uint32_t a2, uint32_t a3,
                                         uint32_t b0, uint32_t b1) {
    asm volatile(
        "mma.sync.aligned.m16n8k8.row.col.f32.tf32.tf32.f32 "
        "{%0,%1,%2,%3}, {%4,%5,%6,%7}, {%8,%9}, {%0,%1,%2,%3};"
        : "+f"(c[0]), "+f"(c[1]), "+f"(c[2]), "+f"(c[3])
        : "r"(a0), "r"(a1), "r"(a2), "r"(a3), "r"(b0), "r"(b1));
}

__device__ __forceinline__ float gelu_exact(float x) {
    return 0.5f * x * (1.0f + erff(x * 0.70710678118654752440f));
}

// ---------------- device scratch ----------------
__device__ __align__(16) float g_key[NC * KD];           // [cell][k]  (tf32-rounded)
__device__ __align__(16) float g_query[NG * KD];         // [gene][k]
__device__ __align__(16) float g_pnum[NSPLIT * ZD * NG]; // [split][z][gene]
__device__ __align__(16) float g_pden[NSPLIT * NG];      // [split][gene]

// ---------------- fused MLP prologue (key: blocks [0,256), query: rest) ----------------
#define KEY_BLOCKS (NC / 32)               // 256
#define QRY_BLOCKS ((NG + 63) / 64)        // 157
#define MLP_BLOCKS (KEY_BLOCKS + QRY_BLOCKS)
#define KP1 52                             // key MLP k-split pass 1 size

__global__ void __launch_bounds__(256, 2)
mlp_fused_kernel(const float* __restrict__ rawZ,
                 const float* __restrict__ Wz1, const float* __restrict__ bz1,
                 const float* __restrict__ Wz2, const float* __restrict__ bz2,
                 const float* __restrict__ Grep,
                 const float* __restrict__ Wg1, const float* __restrict__ bg1,
                 const float* __restrict__ Wg2, const float* __restrict__ bg2) {
    __shared__ float buf[ZD * 32 + 32 * HD];   // 45568 B; query part aliases
    int tid = threadIdx.x;

    if (blockIdx.x < KEY_BLOCKS) {
        // ---- key MLP: 32 cells per block; k-loop split in 2 passes for regs ----
        float* Zs = buf;                 // [k][cc]
        float* Hs = buf + ZD * 32;       // [cc][h]
        int c0 = blockIdx.x * 32;

        for (int idx = tid; idx < ZD * 32; idx += 256) {
            int k = idx >> 5, cc = idx & 31;
            Zs[idx] = rawZ[(size_t)k * NC + c0 + cc];
        }
        __syncthreads();
        {
            int h = tid;
            // pass 1: k in [0, KP1); partial parked in this thread's own Hs slots
            {
                float w[KP1];
                #pragma unroll
                for (int k = 0; k < KP1; ++k) w[k] = Wz1[k * HD + h];
                float b = bz1[h];
                for (int cc = 0; cc < 32; ++cc) {
                    float a = b;
                    #pragma unroll
                    for (int k = 0; k < KP1; ++k) a = fmaf(Zs[k * 32 + cc], w[k], a);
                    Hs[cc * HD + h] = a;
                }
            }
            // pass 2: k in [KP1, ZD); same accumulation order; gelu at end
            {
                float w[ZD - KP1];
                #pragma unroll
                for (int k = 0; k < ZD - KP1; ++k) w[k] = Wz1[(KP1 + k) * HD + h];
                for (int cc = 0; cc < 32; ++cc) {
                    float a = Hs[cc * HD + h];
                    #pragma unroll
                    for (int k = 0; k < ZD - KP1; ++k)
                        a = fmaf(Zs[(KP1 + k) * 32 + cc], w[k], a);
                    Hs[cc * HD + h] = gelu_exact(a);
                }
            }
        }
        __syncthreads();
        for (int idx = tid; idx < 32 * KD; idx += 256) {
            int cc = idx >> 5, kk = idx & 31;
            float a = bz2[kk];
            #pragma unroll 8
            for (int h = 0; h < HD; ++h) a = fmaf(Hs[cc * HD + h], Wz2[h * KD + kk], a);
            g_key[(size_t)(c0 + cc) * KD + kk] = to_tf32(a);
        }
    } else {
        // ---- query MLP: 64 genes per block ----
        float* Gq  = buf;
        float* W1s = buf + 64 * 101;
        float* W2s = W1s + 100 * 32;
        float* b1s = W2s + 32 * 32;
        float* b2s = b1s + 32;
        int g0 = (blockIdx.x - KEY_BLOCKS) * 64;
        int valid = min(64, NG - g0);

        for (int idx = tid; idx < valid * 100; idx += 256) {
            int r = idx / 100, c = idx - r * 100;
            Gq[r * 101 + c] = Grep[(size_t)g0 * 100 + idx];
        }
        for (int idx = tid; idx < 100 * 32; idx += 256) W1s[idx] = Wg1[idx];
        for (int idx = tid; idx < 32 * 32; idx += 256) W2s[idx] = Wg2[idx];
        if (tid < 32) { b1s[tid] = bg1[tid]; b2s[tid] = bg2[tid]; }
        __syncthreads();

        if (tid < valid) {
            float hid[32];
            #pragma unroll
            for (int j = 0; j < 32; ++j) hid[j] = b1s[j];
            for (int k = 0; k < 100; ++k) {
                float gv = Gq[tid * 101 + k];
                #pragma unroll
                for (int j = 0; j < 32; ++j) hid[j] = fmaf(gv, W1s[k * 32 + j], hid[j]);
            }
            #pragma unroll
            for (int j = 0; j < 32; ++j) hid[j] = gelu_exact(hid[j]);
            int g = g0 + tid;
            #pragma unroll 4
            for (int kk = 0; kk < 32; ++kk) {
                float a = b2s[kk];
                #pragma unroll
                for (int j = 0; j < 32; ++j) a = fmaf(hid[j], W2s[j * 32 + kk], a);
                g_query[(size_t)g * KD + kk] = a;
            }
        }
    }
}

// ---------------- main fused kernel ----------------
// smem (floats), single V buffer
#define KS_OFF 0
#define VS_OFF (CT * KSTR)                       // 2304
#define GS_OFF (VS_OFF + 104 * VSTR)             // 9376
#define PS_OFF (GS_OFF + GT * GSTR)              // 18080
#define SMEM_FLOATS (PS_OFF + GT * PSTR)         // 26784
#define SMEM_MAIN (SMEM_FLOATS * 4)              // 107136 B -> 2 CTAs/SM

__global__ void __launch_bounds__(THREADS, 2)
decoder_main_kernel(const float* __restrict__ gumbel,
                    const float* __restrict__ genZ) {
    extern __shared__ float smem[];
    float* Ks = smem + KS_OFF;
    float* Vs = smem + VS_OFF;   // [z][cell]
    float* Gs = smem + GS_OFF;   // [gene][cell] raw gumbel
    float* Ps = smem + PS_OFF;   // [gene][cell]

    int tid = threadIdx.x;
    int wid = tid >> 5;          // 0..7 = m-tile
    int lane = tid & 31;
    int split = blockIdx.y;
    int gbase = blockIdx.x * GT;

    int lr = lane >> 2;
    int lc = lane & 3;
    int arowS = wid * 16 + lr;   // m-tile row for S and PV

    // ldmatrix lane components
    int lt = lane >> 3, lrow = lane & 7;
    uint32_t ks_b = smem_u32(Ks);
    uint32_t vs_b = smem_u32(Vs);
    uint32_t gs_b = smem_u32(Gs);
    uint32_t ps_b = smem_u32(Ps);
    uint32_t k_lane = ks_b + (uint32_t)((lrow * KSTR + lt * 4) * 4);
    uint32_t a_lane = ps_b + (uint32_t)(((((lt & 1) * 8) + lrow) * PSTR + (lt >> 1) * 4) * 4)
                    + (uint32_t)((wid * 16) * PSTR * 4);
    uint32_t b_lane = vs_b + (uint32_t)(((((lt >> 1) * 8) + lrow) * VSTR + (lt & 1) * 4) * 4);
    uint32_t b2_lane = vs_b + (uint32_t)((lrow * VSTR + (lt & 1) * 4) * 4)
                     + (uint32_t)((12 * 8) * VSTR * 4);

    // ---- Q fragments in registers, loaded once (tf32) ----
    uint32_t qf[4][4];
    {
        int gq0 = min(gbase + arowS, NG - 1);
        int gq1 = min(gbase + arowS + 8, NG - 1);
        const float* q0 = g_query + (size_t)gq0 * KD;
        const float* q1 = g_query + (size_t)gq1 * KD;
        #pragma unroll
        for (int k8 = 0; k8 < 4; ++k8) {
            int k = k8 * 8 + lc;
            qf[k8][0] = __float_as_uint(to_tf32(q0[k]));
            qf[k8][1] = __float_as_uint(to_tf32(q1[k]));
            qf[k8][2] = __float_as_uint(to_tf32(q0[k + 4]));
            qf[k8][3] = __float_as_uint(to_tf32(q1[k + 4]));
        }
    }

    // ---- staging helpers ----
    auto stage_K = [&](int cbase) {
        #pragma unroll
        for (int i = 0; i < 2; ++i) {
            int idx = tid + i * THREADS;
            int kc = idx >> 3, kq = idx & 7;
            cpa16(ks_b + (uint32_t)((kc * KSTR + kq * 4) * 4),
                  g_key + (size_t)(cbase + kc) * KD + kq * 4);
        }
    };
    auto stage_V = [&](int cbase) {
        #pragma unroll
        for (int i = 0; i < 7; ++i) {
            int idx = tid + i * THREADS;
            if (idx < ZD * 16) {
                int z = idx >> 4, c4 = idx & 15;
                cpa16(vs_b + (uint32_t)((z * VSTR + c4 * 4) * 4),
                      genZ + (size_t)z * NC + cbase + c4 * 4);
            }
        }
    };
    auto stage_G = [&](int cbase) {
        #pragma unroll
        for (int i = 0; i < 8; ++i) {
            int idx = tid + i * THREADS;
            int gr = idx >> 4, c4 = idx & 15;
            int grow = min(gbase + gr, NG - 1);
            cpa16(gs_b + (uint32_t)((gr * GSTR + c4 * 4) * 4),
                  gumbel + (size_t)grow * NC + cbase + c4 * 4);
        }
    };

    float acc[13][4];
    #pragma unroll
    for (int i = 0; i < 13; ++i) {
        acc[i][0] = 0.f; acc[i][1] = 0.f;
        acc[i][2] = 0.f; acc[i][3] = 0.f;
    }

    // ---- prologue: stage chunk 0; fill V pad rows once ----
    int cbase0 = split * CPC;
    stage_K(cbase0);
    stage_V(cbase0);
    stage_G(cbase0);
    CPA_COMMIT();
    if (tid < 64) {
        int zr = tid >> 4, c4 = tid & 15;   // z = 100..103
        float4 v = (zr == 0) ? make_float4(1.f, 1.f, 1.f, 1.f)
                             : make_float4(0.f, 0.f, 0.f, 0.f);
        *reinterpret_cast<float4*>(Vs + (ZD + zr) * VSTR + c4 * 4) = v;
    }
    CPA_WAIT0();
    __syncthreads();

    for (int t = 0; t < NCHUNK; ++t) {
        // ---- phase S: this warp's m-tile x 8 cell tiles ----
        #pragma unroll
        for (int nt = 0; nt < CT / 8; ++nt) {
            uint32_t kb[8];
            uint32_t ka = k_lane + (uint32_t)(nt * 8 * KSTR * 4);
            ldmx4(kb, ka);
            ldmx4(kb + 4, ka + 64);
            float sacc[4] = {0.f, 0.f, 0.f, 0.f};
            mma_tf32(sacc, qf[0][0], qf[0][1], qf[0][2], qf[0][3], kb[0], kb[1]);
            mma_tf32(sacc, qf[1][0], qf[1][1], qf[1][2], qf[1][3], kb[2], kb[3]);
            mma_tf32(sacc, qf[2][0], qf[2][1], qf[2][2], qf[2][3], kb[4], kb[5]);
            mma_tf32(sacc, qf[3][0], qf[3][1], qf[3][2], qf[3][3], kb[6], kb[7]);
            int c0 = nt * 8 + 2 * lc;
            float2 gA = *reinterpret_cast<const float2*>(Gs + arowS * GSTR + c0);
            float2 gB = *reinterpret_cast<const float2*>(Gs + (arowS + 8) * GSTR + c0);
            float2 pA, pB;
            pA.x = exp2f(fmaf(gA.x, L2E, sacc[0] * SCALE_S));
            pA.y = exp2f(fmaf(gA.y, L2E, sacc[1] * SCALE_S));
            pB.x = exp2f(fmaf(gB.x, L2E, sacc[2] * SCALE_S));
            pB.y = exp2f(fmaf(gB.y, L2E, sacc[3] * SCALE_S));
            *reinterpret_cast<float2*>(Ps + arowS * PSTR + c0) = pA;
            *reinterpret_cast<float2*>(Ps + (arowS + 8) * PSTR + c0) = pB;
        }
        __syncthreads();   // Ps ready; Ks, Gs dead

        // ---- prefetch K/G of chunk t+1 into dead buffers ----
        if (t + 1 < NCHUNK) {
            int cb = split * CPC + (t + 1) * CT;
            stage_K(cb);
            stage_G(cb);
            CPA_COMMIT();
            CPA_WAIT1();   // retire V(t); KG(t+1) may stay in flight
        } else {
            CPA_WAIT0();   // last chunk: make sure V(t) complete
        }

        // ---- phase PV: D += P @ V_ext^T (13 n-tiles) ----
        #pragma unroll
        for (int k8 = 0; k8 < CT / 8; ++k8) {
            uint32_t k0b = (uint32_t)(k8 * 8 * 4);
            uint32_t af0[4];
            ldmx4(af0, a_lane + k0b);
            #pragma unroll
            for (int p = 0; p < 6; ++p) {
                uint32_t bf[4];
                ldmx4(bf, b_lane + (uint32_t)((2 * p * 8) * VSTR * 4) + k0b);
                mma_tf32(acc[2 * p],     af0[0], af0[1], af0[2], af0[3], bf[0], bf[1]);
                mma_tf32(acc[2 * p + 1], af0[0], af0[1], af0[2], af0[3], bf[2], bf[3]);
            }
            {
                uint32_t bf2[2];
                ldmx2(bf2, b2_lane + k0b);
                mma_tf32(acc[12], af0[0], af0[1], af0[2], af0[3], bf2[0], bf2[1]);
            }
        }
        if (t + 1 < NCHUNK) { CPA_WAIT0(); }   // KG(t+1) complete
        __syncthreads();   // PV done; Ps/Vs dead; KG(t+1) visible

        // ---- stage V of chunk t+1 (own group; completes during next S) ----
        if (t + 1 < NCHUNK) {
            stage_V(split * CPC + (t + 1) * CT);
            CPA_COMMIT();
        }
    }

    // ---- epilogue: scatter D fragments to split partials ----
    {
        float* pbase = g_pnum + (size_t)split * (ZD * NG);
        float* dbase = g_pden + split * NG;
        int gl = gbase + wid * 16 + lr;
        int gh = gl + 8;
        #pragma unroll
        for (int nt = 0; nt < 13; ++nt) {
            int z0 = nt * 8 + 2 * lc;
            #pragma unroll
            for (int zz = 0; zz < 2; ++zz) {
                int z = z0 + zz;
                if (z < ZD) {
                    if (gl < NG) pbase[(size_t)z * NG + gl] = acc[nt][zz];
                    if (gh < NG) pbase[(size_t)z * NG + gh] = acc[nt][2 + zz];
                } else if (z == ZD) {
                    if (gl < NG) dbase[gl] = acc[nt][zz];
                    if (gh < NG) dbase[gh] = acc[nt][2 + zz];
                }
            }
        }
    }
}

// ---------------- fused reduce: block = 64 genes x all z; den summed once ----------------
#define RG 64
__global__ void __launch_bounds__(256)
reduce_kernel(float* __restrict__ out) {
    __shared__ float dens[RG];
    int g0 = blockIdx.x * RG;
    int tid = threadIdx.x;

    if (tid < RG) {
        int g = g0 + tid;
        float d = 0.f;
        if (g < NG) {
            #pragma unroll
            for (int s = 0; s < NSPLIT; ++s) d += g_pden[s * NG + g];
        }
        dens[tid] = d;
    }
    __syncthreads();

    const int q_per_row = RG / 4;                 // 16 float4 per z row
    for (int it = tid; it < ZD * q_per_row; it += 256) {
        int z = it / q_per_row;
        int gq = it - z * q_per_row;
        int gg = g0 + gq * 4;
        if (gg >= NG) continue;                   // NG % 4 == 0 -> whole float4 valid
        float4 n = make_float4(0.f, 0.f, 0.f, 0.f);
        #pragma unroll
        for (int s = 0; s < NSPLIT; ++s) {
            float4 a = *reinterpret_cast<const float4*>(
                g_pnum + (size_t)s * (ZD * NG) + (size_t)z * NG + gg);
            n.x += a.x; n.y += a.y; n.z += a.z; n.w += a.w;
        }
        float4 o;
        o.x = n.x / dens[gq * 4 + 0];
        o.y = n.y / dens[gq * 4 + 1];
        o.z = n.z / dens[gq * 4 + 2];
        o.w = n.w / dens[gq * 4 + 3];
        *reinterpret_cast<float4*>(out + (size_t)z * NG + gg) = o;
    }
}

// ---------------- launch ----------------
extern "C" void kernel_launch(void* const* d_in, const int* in_sizes, int n_in,
                              void* d_out, int out_size) {
    const float* rawZ   = (const float*)d_in[0];
    const float* genZ   = (const float*)d_in[1];
    const float* Grep   = (const float*)d_in[2];
    const float* gumbel = (const float*)d_in[3];
    const float* Wz1 = (const float*)d_in[4];
    const float* bz1 = (const float*)d_in[5];
    const float* Wz2 = (const float*)d_in[6];
    const float* bz2 = (const float*)d_in[7];
    const float* Wg1 = (const float*)d_in[8];
    const float* bg1 = (const float*)d_in[9];
    const float* Wg2 = (const float*)d_in[10];
    const float* bg2 = (const float*)d_in[11];
    float* out = (float*)d_out;

    cudaFuncSetAttribute(decoder_main_kernel,
                         cudaFuncAttributeMaxDynamicSharedMemorySize, SMEM_MAIN);

    mlp_fused_kernel<<<MLP_BLOCKS, 256>>>(rawZ, Wz1, bz1, Wz2, bz2,
                                          Grep, Wg1, bg1, Wg2, bg2);

    dim3 grid((NG + GT - 1) / GT, NSPLIT);
    decoder_main_kernel<<<grid, THREADS, SMEM_MAIN>>>(gumbel, genZ);

    reduce_kernel<<<(NG + RG - 1) / RG, 256>>>(out);
}

// round 14
// speedup vs baseline: 1.0002x; 1.0002x over previous
#include <cuda_runtime.h>
#include <math.h>
#include <stdint.h>

#define NG 10000      // genes
#define NC 8192       // cells
#define ZD 100        // z dim
#define KD 32         // key dim
#define HD 256        // hidden dim (key MLP)
#define GT 128        // genes per CTA (= M)
#define CT 64         // cells per chunk
#define NSPLIT 16     // cell splits
#define CPC (NC / NSPLIT)        // 512 cells per CTA
#define NCHUNK (CPC / CT)        // 8 chunks
#define THREADS 256

#define KSTR 36       // Ks row stride (floats)
#define VSTR 68       // Vs row stride (z-major: [z][cell])
#define GSTR 68       // Gs row stride
#define PSTR 68       // Ps row stride

// log2(e), log2(e)/sqrt(32)
#define L2E 1.4426950408889634f
#define SCALE_S 0.25503482f

typedef unsigned long long u64;

__device__ __forceinline__ uint32_t smem_u32(const void* p) {
    uint32_t a;
    asm("{ .reg .u64 t; cvta.to.shared.u64 t, %1; cvt.u32.u64 %0, t; }" : "=r"(a) : "l"(p));
    return a;
}

__device__ __forceinline__ float to_tf32(float x) {
    uint32_t r;
    asm("cvt.rna.tf32.f32 %0, %1;" : "=r"(r) : "f"(x));
    return __uint_as_float(r);
}

__device__ __forceinline__ void cpa16(uint32_t dst, const void* src) {
    asm volatile("cp.async.cg.shared.global [%0], [%1], 16;" :: "r"(dst), "l"(src));
}
#define CPA_COMMIT() asm volatile("cp.async.commit_group;" ::: "memory")
#define CPA_WAIT0()  asm volatile("cp.async.wait_group 0;" ::: "memory")
#define CPA_WAIT1()  asm volatile("cp.async.wait_group 1;" ::: "memory")

__device__ __forceinline__ void ldmx4(uint32_t* r, uint32_t addr) {
    asm volatile("ldmatrix.sync.aligned.m8n8.x4.shared.b16 {%0,%1,%2,%3}, [%4];"
        : "=r"(r[0]), "=r"(r[1]), "=r"(r[2]), "=r"(r[3]) : "r"(addr));
}
__device__ __forceinline__ void ldmx2(uint32_t* r, uint32_t addr) {
    asm volatile("ldmatrix.sync.aligned.m8n8.x2.shared.b16 {%0,%1}, [%2];"
        : "=r"(r[0]), "=r"(r[1]) : "r"(addr));
}

// m16n8k8 tf32 mma, C=D accum
__device__ __forceinline__ void mma_tf32(float* c,
                                         uint32_t a0, uint32_t a1, uint32_t a2, uint32_t a3,
                                         uint32_t b0, uint32_t b1) {
    asm volatile(
        "mma.sync.aligned.m16n8k8.row.col.f32.tf32.tf32.f32 "
        "{%0,%1,%2,%3}, {%4,%5,%6,%7}, {%8,%9}, {%0,%1,%2,%3};"
        : "+f"(c[0]), "+f"(c[1]), "+f"(c[2]), "+f"(c[3])
        : "r"(a0), "r"(a1), "r"(a2), "r"(a3), "r"(b0), "r"(b1));
}

__device__ __forceinline__ float gelu_exact(float x) {
    return 0.5f * x * (1.0f + erff(x * 0.70710678118654752440f));
}

// ---------------- device scratch ----------------
__device__ __align__(16) float g_key[NC * KD];           // [cell][k]  (tf32-rounded)
__device__ __align__(16) float g_query[NG * KD];         // [gene][k]
__device__ __align__(16) float g_pnum[NSPLIT * ZD * NG]; // [split][z][gene]
__device__ __align__(16) float g_pden[NSPLIT * NG];      // [split][gene]

// ---------------- fused MLP prologue (key: blocks [0,256), query: rest) ----------------
#define KEY_BLOCKS (NC / 32)               // 256
#define QRY_BLOCKS ((NG + 63) / 64)        // 157
#define MLP_BLOCKS (KEY_BLOCKS + QRY_BLOCKS)
#define KP1 52                             // key MLP k-split pass 1 size

__global__ void __launch_bounds__(256, 2)
mlp_fused_kernel(const float* __restrict__ rawZ,
                 const float* __restrict__ Wz1, const float* __restrict__ bz1,
                 const float* __restrict__ Wz2, const float* __restrict__ bz2,
                 const float* __restrict__ Grep,
                 const float* __restrict__ Wg1, const float* __restrict__ bg1,
                 const float* __restrict__ Wg2, const float* __restrict__ bg2) {
    __shared__ float buf[ZD * 32 + 32 * HD];   // 45568 B; query part aliases
    int tid = threadIdx.x;

    if (blockIdx.x < KEY_BLOCKS) {
        // ---- key MLP: 32 cells per block; 2 k-passes; 4-cell ILP + LDS.128 ----
        float* Zs = buf;                 // [k][cc]  (row = 32 floats, float4-aligned)
        float* Hs = buf + ZD * 32;       // [cc][h]
        int c0 = blockIdx.x * 32;

        for (int idx = tid; idx < ZD * 32; idx += 256) {
            int k = idx >> 5, cc = idx & 31;
            Zs[idx] = rawZ[(size_t)k * NC + c0 + cc];
        }
        __syncthreads();
        {
            int h = tid;
            // pass 1: k in [0, KP1); 4 cells at a time (independent chains)
            {
                float w[KP1];
                #pragma unroll
                for (int k = 0; k < KP1; ++k) w[k] = Wz1[k * HD + h];
                float b = bz1[h];
                #pragma unroll
                for (int cc4 = 0; cc4 < 32; cc4 += 4) {
                    float a0 = b, a1 = b, a2 = b, a3 = b;
                    #pragma unroll
                    for (int k = 0; k < KP1; ++k) {
                        float4 z = *reinterpret_cast<const float4*>(Zs + k * 32 + cc4);
                        a0 = fmaf(z.x, w[k], a0);
                        a1 = fmaf(z.y, w[k], a1);
                        a2 = fmaf(z.z, w[k], a2);
                        a3 = fmaf(z.w, w[k], a3);
                    }
                    Hs[(cc4 + 0) * HD + h] = a0;
                    Hs[(cc4 + 1) * HD + h] = a1;
                    Hs[(cc4 + 2) * HD + h] = a2;
                    Hs[(cc4 + 3) * HD + h] = a3;
                }
            }
            // pass 2: k in [KP1, ZD); same per-cell accumulation order; gelu at end
            {
                float w[ZD - KP1];
                #pragma unroll
                for (int k = 0; k < ZD - KP1; ++k) w[k] = Wz1[(KP1 + k) * HD + h];
                #pragma unroll
                for (int cc4 = 0; cc4 < 32; cc4 += 4) {
                    float a0 = Hs[(cc4 + 0) * HD + h];
                    float a1 = Hs[(cc4 + 1) * HD + h];
                    float a2 = Hs[(cc4 + 2) * HD + h];
                    float a3 = Hs[(cc4 + 3) * HD + h];
                    #pragma unroll
                    for (int k = 0; k < ZD - KP1; ++k) {
                        float4 z = *reinterpret_cast<const float4*>(Zs + (KP1 + k) * 32 + cc4);
                        a0 = fmaf(z.x, w[k], a0);
                        a1 = fmaf(z.y, w[k], a1);
                        a2 = fmaf(z.z, w[k], a2);
                        a3 = fmaf(z.w, w[k], a3);
                    }
                    Hs[(cc4 + 0) * HD + h] = gelu_exact(a0);
                    Hs[(cc4 + 1) * HD + h] = gelu_exact(a1);
                    Hs[(cc4 + 2) * HD + h] = gelu_exact(a2);
                    Hs[(cc4 + 3) * HD + h] = gelu_exact(a3);
                }
            }
        }
        __syncthreads();
        for (int idx = tid; idx < 32 * KD; idx += 256) {
            int cc = idx >> 5, kk = idx & 31;
            float a = bz2[kk];
            #pragma unroll 8
            for (int h = 0; h < HD; ++h) a = fmaf(Hs[cc * HD + h], Wz2[h * KD + kk], a);
            g_key[(size_t)(c0 + cc) * KD + kk] = to_tf32(a);
        }
    } else {
        // ---- query MLP: 64 genes per block ----
        float* Gq  = buf;
        float* W1s = buf + 64 * 101;
        float* W2s = W1s + 100 * 32;
        float* b1s = W2s + 32 * 32;
        float* b2s = b1s + 32;
        int g0 = (blockIdx.x - KEY_BLOCKS) * 64;
        int valid = min(64, NG - g0);

        for (int idx = tid; idx < valid * 100; idx += 256) {
            int r = idx / 100, c = idx - r * 100;
            Gq[r * 101 + c] = Grep[(size_t)g0 * 100 + idx];
        }
        for (int idx = tid; idx < 100 * 32; idx += 256) W1s[idx] = Wg1[idx];
        for (int idx = tid; idx < 32 * 32; idx += 256) W2s[idx] = Wg2[idx];
        if (tid < 32) { b1s[tid] = bg1[tid]; b2s[tid] = bg2[tid]; }
        __syncthreads();

        if (tid < valid) {
            float hid[32];
            #pragma unroll
            for (int j = 0; j < 32; ++j) hid[j] = b1s[j];
            for (int k = 0; k < 100; ++k) {
                float gv = Gq[tid * 101 + k];
                #pragma unroll
                for (int j = 0; j < 32; ++j) hid[j] = fmaf(gv, W1s[k * 32 + j], hid[j]);
            }
            #pragma unroll
            for (int j = 0; j < 32; ++j) hid[j] = gelu_exact(hid[j]);
            int g = g0 + tid;
            #pragma unroll 4
            for (int kk = 0; kk < 32; ++kk) {
                float a = b2s[kk];
                #pragma unroll
                for (int j = 0; j < 32; ++j) a = fmaf(hid[j], W2s[j * 32 + kk], a);
                g_query[(size_t)g * KD + kk] = a;
            }
        }
    }
}

// ---------------- main fused kernel ----------------
// smem (floats), single V buffer
#define KS_OFF 0
#define VS_OFF (CT * KSTR)                       // 2304
#define GS_OFF (VS_OFF + 104 * VSTR)             // 9376
#define PS_OFF (GS_OFF + GT * GSTR)              // 18080
#define SMEM_FLOATS (PS_OFF + GT * PSTR)         // 26784
#define SMEM_MAIN (SMEM_FLOATS * 4)              // 107136 B -> 2 CTAs/SM

__global__ void __launch_bounds__(THREADS, 2)
decoder_main_kernel(const float* __restrict__ gumbel,
                    const float* __restrict__ genZ) {
    extern __shared__ float smem[];
    float* Ks = smem + KS_OFF;
    float* Vs = smem + VS_OFF;   // [z][cell]
    float* Gs = smem + GS_OFF;   // [gene][cell] raw gumbel
    float* Ps = smem + PS_OFF;   // [gene][cell]

    int tid = threadIdx.x;
    int wid = tid >> 5;          // 0..7 = m-tile
    int lane = tid & 31;
    int split = blockIdx.y;
    int gbase = blockIdx.x * GT;

    int lr = lane >> 2;
    int lc = lane & 3;
    int arowS = wid * 16 + lr;   // m-tile row for S and PV

    // ldmatrix lane components
    int lt = lane >> 3, lrow = lane & 7;
    uint32_t ks_b = smem_u32(Ks);
    uint32_t vs_b = smem_u32(Vs);
    uint32_t gs_b = smem_u32(Gs);
    uint32_t ps_b = smem_u32(Ps);
    uint32_t k_lane = ks_b + (uint32_t)((lrow * KSTR + lt * 4) * 4);
    uint32_t a_lane = ps_b + (uint32_t)(((((lt & 1) * 8) + lrow) * PSTR + (lt >> 1) * 4) * 4)
                    + (uint32_t)((wid * 16) * PSTR * 4);
    uint32_t b_lane = vs_b + (uint32_t)(((((lt >> 1) * 8) + lrow) * VSTR + (lt & 1) * 4) * 4);
    uint32_t b2_lane = vs_b + (uint32_t)((lrow * VSTR + (lt & 1) * 4) * 4)
                     + (uint32_t)((12 * 8) * VSTR * 4);

    // ---- Q fragments in registers, loaded once (tf32) ----
    uint32_t qf[4][4];
    {
        int gq0 = min(gbase + arowS, NG - 1);
        int gq1 = min(gbase + arowS + 8, NG - 1);
        const float* q0 = g_query + (size_t)gq0 * KD;
        const float* q1 = g_query + (size_t)gq1 * KD;
        #pragma unroll
        for (int k8 = 0; k8 < 4; ++k8) {
            int k = k8 * 8 + lc;
            qf[k8][0] = __float_as_uint(to_tf32(q0[k]));
            qf[k8][1] = __float_as_uint(to_tf32(q1[k]));
            qf[k8][2] = __float_as_uint(to_tf32(q0[k + 4]));
            qf[k8][3] = __float_as_uint(to_tf32(q1[k + 4]));
        }
    }

    // ---- staging helpers ----
    auto stage_K = [&](int cbase) {
        #pragma unroll
        for (int i = 0; i < 2; ++i) {
            int idx = tid + i * THREADS;
            int kc = idx >> 3, kq = idx & 7;
            cpa16(ks_b + (uint32_t)((kc * KSTR + kq * 4) * 4),
                  g_key + (size_t)(cbase + kc) * KD + kq * 4);
        }
    };
    auto stage_V = [&](int cbase) {
        #pragma unroll
        for (int i = 0; i < 7; ++i) {
            int idx = tid + i * THREADS;
            if (idx < ZD * 16) {
                int z = idx >> 4, c4 = idx & 15;
                cpa16(vs_b + (uint32_t)((z * VSTR + c4 * 4) * 4),
                      genZ + (size_t)z * NC + cbase + c4 * 4);
            }
        }
    };
    auto stage_G = [&](int cbase) {
        #pragma unroll
        for (int i = 0; i < 8; ++i) {
            int idx = tid + i * THREADS;
            int gr = idx >> 4, c4 = idx & 15;
            int grow = min(gbase + gr, NG - 1);
            cpa16(gs_b + (uint32_t)((gr * GSTR + c4 * 4) * 4),
                  gumbel + (size_t)grow * NC + cbase + c4 * 4);
        }
    };

    float acc[13][4];
    #pragma unroll
    for (int i = 0; i < 13; ++i) {
        acc[i][0] = 0.f; acc[i][1] = 0.f;
        acc[i][2] = 0.f; acc[i][3] = 0.f;
    }

    // ---- prologue: stage chunk 0; fill V pad rows once ----
    int cbase0 = split * CPC;
    stage_K(cbase0);
    stage_V(cbase0);
    stage_G(cbase0);
    CPA_COMMIT();
    if (tid < 64) {
        int zr = tid >> 4, c4 = tid & 15;   // z = 100..103
        float4 v = (zr == 0) ? make_float4(1.f, 1.f, 1.f, 1.f)
                             : make_float4(0.f, 0.f, 0.f, 0.f);
        *reinterpret_cast<float4*>(Vs + (ZD + zr) * VSTR + c4 * 4) = v;
    }
    CPA_WAIT0();
    __syncthreads();

    for (int t = 0; t < NCHUNK; ++t) {
        // ---- phase S: this warp's m-tile x 8 cell tiles ----
        #pragma unroll
        for (int nt = 0; nt < CT / 8; ++nt) {
            uint32_t kb[8];
            uint32_t ka = k_lane + (uint32_t)(nt * 8 * KSTR * 4);
            ldmx4(kb, ka);
            ldmx4(kb + 4, ka + 64);
            float sacc[4] = {0.f, 0.f, 0.f, 0.f};
            mma_tf32(sacc, qf[0][0], qf[0][1], qf[0][2], qf[0][3], kb[0], kb[1]);
            mma_tf32(sacc, qf[1][0], qf[1][1], qf[1][2], qf[1][3], kb[2], kb[3]);
            mma_tf32(sacc, qf[2][0], qf[2][1], qf[2][2], qf[2][3], kb[4], kb[5]);
            mma_tf32(sacc, qf[3][0], qf[3][1], qf[3][2], qf[3][3], kb[6], kb[7]);
            int c0 = nt * 8 + 2 * lc;
            float2 gA = *reinterpret_cast<const float2*>(Gs + arowS * GSTR + c0);
            float2 gB = *reinterpret_cast<const float2*>(Gs + (arowS + 8) * GSTR + c0);
            float2 pA, pB;
            pA.x = exp2f(fmaf(gA.x, L2E, sacc[0] * SCALE_S));
            pA.y = exp2f(fmaf(gA.y, L2E, sacc[1] * SCALE_S));
            pB.x = exp2f(fmaf(gB.x, L2E, sacc[2] * SCALE_S));
            pB.y = exp2f(fmaf(gB.y, L2E, sacc[3] * SCALE_S));
            *reinterpret_cast<float2*>(Ps + arowS * PSTR + c0) = pA;
            *reinterpret_cast<float2*>(Ps + (arowS + 8) * PSTR + c0) = pB;
        }
        __syncthreads();   // Ps ready; Ks, Gs dead

        // ---- prefetch K/G of chunk t+1 into dead buffers ----
        if (t + 1 < NCHUNK) {
            int cb = split * CPC + (t + 1) * CT;
            stage_K(cb);
            stage_G(cb);
            CPA_COMMIT();
            CPA_WAIT1();   // retire V(t); KG(t+1) may stay in flight
        } else {
            CPA_WAIT0();   // last chunk: make sure V(t) complete
        }

        // ---- phase PV: D += P @ V_ext^T (13 n-tiles) ----
        #pragma unroll
        for (int k8 = 0; k8 < CT / 8; ++k8) {
            uint32_t k0b = (uint32_t)(k8 * 8 * 4);
            uint32_t af0[4];
            ldmx4(af0, a_lane + k0b);
            #pragma unroll
            for (int p = 0; p < 6; ++p) {
                uint32_t bf[4];
                ldmx4(bf, b_lane + (uint32_t)((2 * p * 8) * VSTR * 4) + k0b);
                mma_tf32(acc[2 * p],     af0[0], af0[1], af0[2], af0[3], bf[0], bf[1]);
                mma_tf32(acc[2 * p + 1], af0[0], af0[1], af0[2], af0[3], bf[2], bf[3]);
            }
            {
                uint32_t bf2[2];
                ldmx2(bf2, b2_lane + k0b);
                mma_tf32(acc[12], af0[0], af0[1], af0[2], af0[3], bf2[0], bf2[1]);
            }
        }
        if (t + 1 < NCHUNK) { CPA_WAIT0(); }   // KG(t+1) complete
        __syncthreads();   // PV done; Ps/Vs dead; KG(t+1) visible

        // ---- stage V of chunk t+1 (own group; completes during next S) ----
        if (t + 1 < NCHUNK) {
            stage_V(split * CPC + (t + 1) * CT);
            CPA_COMMIT();
        }
    }

    // ---- epilogue: scatter D fragments to split partials ----
    {
        float* pbase = g_pnum + (size_t)split * (ZD * NG);
        float* dbase = g_pden + split * NG;
        int gl = gbase + wid * 16 + lr;
        int gh = gl + 8;
        #pragma unroll
        for (int nt = 0; nt < 13; ++nt) {
            int z0 = nt * 8 + 2 * lc;
            #pragma unroll
            for (int zz = 0; zz < 2; ++zz) {
                int z = z0 + zz;
                if (z < ZD) {
                    if (gl < NG) pbase[(size_t)z * NG + gl] = acc[nt][zz];
                    if (gh < NG) pbase[(size_t)z * NG + gh] = acc[nt][2 + zz];
                } else if (z == ZD) {
                    if (gl < NG) dbase[gl] = acc[nt][zz];
                    if (gh < NG) dbase[gh] = acc[nt][2 + zz];
                }
            }
        }
    }
}

// ---------------- fused reduce: block = 64 genes x all z; den summed once ----------------
#define RG 64
__global__ void __launch_bounds__(256)
reduce_kernel(float* __restrict__ out) {
    __shared__ float dens[RG];
    int g0 = blockIdx.x * RG;
    int tid = threadIdx.x;

    if (tid < RG) {
        int g = g0 + tid;
        float d = 0.f;
        if (g < NG) {
            #pragma unroll
            for (int s = 0; s < NSPLIT; ++s) d += g_pden[s * NG + g];
        }
        dens[tid] = d;
    }
    __syncthreads();

    const int q_per_row = RG / 4;                 // 16 float4 per z row
    for (int it = tid; it < ZD * q_per_row; it += 256) {
        int z = it / q_per_row;
        int gq = it - z * q_per_row;
        int gg = g0 + gq * 4;
        if (gg >= NG) continue;                   // NG % 4 == 0 -> whole float4 valid
        float4 n = make_float4(0.f, 0.f, 0.f, 0.f);
        #pragma unroll
        for (int s = 0; s < NSPLIT; ++s) {
            float4 a = *reinterpret_cast<const float4*>(
                g_pnum + (size_t)s * (ZD * NG) + (size_t)z * NG + gg);
            n.x += a.x; n.y += a.y; n.z += a.z; n.w += a.w;
        }
        float4 o;
        o.x = n.x / dens[gq * 4 + 0];
        o.y = n.y / dens[gq * 4 + 1];
        o.z = n.z / dens[gq * 4 + 2];
        o.w = n.w / dens[gq * 4 + 3];
        *reinterpret_cast<float4*>(out + (size_t)z * NG + gg) = o;
    }
}

// ---------------- launch ----------------
extern "C" void kernel_launch(void* const* d_in, const int* in_sizes, int n_in,
                              void* d_out, int out_size) {
    const float* rawZ   = (const float*)d_in[0];
    const float* genZ   = (const float*)d_in[1];
    const float* Grep   = (const float*)d_in[2];
    const float* gumbel = (const float*)d_in[3];
    const float* Wz1 = (const float*)d_in[4];
    const float* bz1 = (const float*)d_in[5];
    const float* Wz2 = (const float*)d_in[6];
    const float* bz2 = (const float*)d_in[7];
    const float* Wg1 = (const float*)d_in[8];
    const float* bg1 = (const float*)d_in[9];
    const float* Wg2 = (const float*)d_in[10];
    const float* bg2 = (const float*)d_in[11];
    float* out = (float*)d_out;

    cudaFuncSetAttribute(decoder_main_kernel,
                         cudaFuncAttributeMaxDynamicSharedMemorySize, SMEM_MAIN);

    mlp_fused_kernel<<<MLP_BLOCKS, 256>>>(rawZ, Wz1, bz1, Wz2, bz2,
                                          Grep, Wg1, bg1, Wg2, bg2);

    dim3 grid((NG + GT - 1) / GT, NSPLIT);
    decoder_main_kernel<<<grid, THREADS, SMEM_MAIN>>>(gumbel, genZ);

    reduce_kernel<<<(NG + RG - 1) / RG, 256>>>(out);
}